// round 13
// baseline (speedup 1.0000x reference)
#include <cuda_runtime.h>
#include <cuda_fp16.h>
#include <math.h>
#include <stdint.h>

#define DIMC 768
#define NHEADS 12
#define HD 64
#define HIDDENC 3072
#define SEQ 2048
#define BATCH 2
#define ROWS (BATCH * SEQ)   // 4096

// ---------------- scratch (device globals) ----------------
__device__ __half g_aH[ROWS * DIMC];
__device__ __half g_aL[ROWS * DIMC];
__device__ __half g_fH[ROWS * HIDDENC];
__device__ __half g_fL[ROWS * HIDDENC];
__device__ __half g_qkvH[ROWS * 3 * DIMC];
__device__ __half g_qkvL[ROWS * 3 * DIMC];   // lo only used for Q region
__device__ __half g_wqkv[3 * DIMC * DIMC];
__device__ __half g_wproj[DIMC * DIMC];
__device__ __half g_wfc1[HIDDENC * DIMC];
__device__ __half g_wfc2[DIMC * HIDDENC];

// ---------------- helpers ----------------
__device__ __forceinline__ uint32_t smem_u32(const void* p) {
    uint32_t a;
    asm("{ .reg .u64 t; cvta.to.shared.u64 t, %1; cvt.u32.u64 %0, t; }" : "=r"(a) : "l"(p));
    return a;
}
__device__ __forceinline__ void cpa16(uint32_t dst, const void* src) {
    asm volatile("cp.async.cg.shared.global [%0], [%1], 16;" :: "r"(dst), "l"(src));
}
#define CP_COMMIT() asm volatile("cp.async.commit_group;" ::: "memory")
#define CP_WAIT(n)  asm volatile("cp.async.wait_group %0;" :: "n"(n) : "memory")

#define LDSM4(r, a) \
    asm volatile("ldmatrix.sync.aligned.m8n8.x4.shared.b16 {%0,%1,%2,%3}, [%4];" \
        : "=r"((r)[0]), "=r"((r)[1]), "=r"((r)[2]), "=r"((r)[3]) : "r"(a))
#define LDSM4T(r, a) \
    asm volatile("ldmatrix.sync.aligned.m8n8.x4.trans.shared.b16 {%0,%1,%2,%3}, [%4];" \
        : "=r"((r)[0]), "=r"((r)[1]), "=r"((r)[2]), "=r"((r)[3]) : "r"(a))

#define MMAF16(d, a, b) \
    asm volatile("mma.sync.aligned.m16n8k16.row.col.f32.f16.f16.f32 " \
        "{%0,%1,%2,%3}, {%4,%5,%6,%7}, {%8,%9}, {%0,%1,%2,%3};" \
        : "+f"((d)[0]), "+f"((d)[1]), "+f"((d)[2]), "+f"((d)[3]) \
        : "r"((a)[0]), "r"((a)[1]), "r"((a)[2]), "r"((a)[3]), "r"((b)[0]), "r"((b)[1]))

__device__ __forceinline__ void split2h(float v, __half& h, __half& l) {
    h = __float2half_rn(v);
    l = __float2half_rn(v - __half2float(h));
}
__device__ __forceinline__ uint32_t packsplith(float a, float b, uint32_t& lo) {
    __half ah, al, bh, bl;
    split2h(a, ah, al);
    split2h(b, bh, bl);
    lo = (uint32_t)__half_as_ushort(al) | ((uint32_t)__half_as_ushort(bl) << 16);
    return (uint32_t)__half_as_ushort(ah) | ((uint32_t)__half_as_ushort(bh) << 16);
}
__device__ __forceinline__ uint32_t pack16(float a, float b) {
    return (uint32_t)__half_as_ushort(__float2half_rn(a)) |
           ((uint32_t)__half_as_ushort(__float2half_rn(b)) << 16);
}

// gemm tile swizzle: [128][32] fp16 packed in 64 x 128B rows
__device__ __forceinline__ uint32_t swz(int r, int c) {
    int p = r >> 1;
    int sub = ((r & 1) << 2) + (c >> 3);
    return (uint32_t)(p * 128 + (((sub ^ (p & 7)) << 4)) + ((c & 7) << 1));
}
// attention tile swizzle: [.][64] fp16, 128B per row (byte offset)
__device__ __forceinline__ uint32_t asw(int r, int c) {
    return (uint32_t)(r * 128 + ((((c >> 3) ^ (r & 7)) << 4)) + ((c & 7) << 1));
}

// ---------------- LayerNorm -> fp16 hi/lo split ----------------
__global__ void ln_split(const float* __restrict__ x,
                         const float* __restrict__ g,
                         const float* __restrict__ b,
                         __half* __restrict__ oh,
                         __half* __restrict__ ol) {
    int row = blockIdx.x;
    const float* xr = x + (size_t)row * DIMC;
    float s = 0.f, s2 = 0.f;
    for (int i = threadIdx.x; i < DIMC; i += 256) {
        float v = xr[i];
        s += v; s2 += v * v;
    }
    #pragma unroll
    for (int o = 16; o; o >>= 1) {
        s  += __shfl_xor_sync(0xffffffffu, s,  o);
        s2 += __shfl_xor_sync(0xffffffffu, s2, o);
    }
    __shared__ float sm[8], sq[8];
    __shared__ float mu_s, rs_s;
    int w = threadIdx.x >> 5, l = threadIdx.x & 31;
    if (l == 0) { sm[w] = s; sq[w] = s2; }
    __syncthreads();
    if (threadIdx.x == 0) {
        float S = 0.f, S2 = 0.f;
        #pragma unroll
        for (int i = 0; i < 8; i++) { S += sm[i]; S2 += sq[i]; }
        float mu = S / DIMC;
        float var = S2 / DIMC - mu * mu;
        mu_s = mu;
        rs_s = rsqrtf(var + 1e-5f);
    }
    __syncthreads();
    float mu = mu_s, rs = rs_s;
    for (int i = threadIdx.x; i < DIMC; i += 256) {
        float v = (xr[i] - mu) * rs * g[i] + b[i];
        __half h, lo;
        split2h(v, h, lo);
        oh[(size_t)row * DIMC + i] = h;
        ol[(size_t)row * DIMC + i] = lo;
    }
}

// ---------------- weight transpose: w[K,N] fp32 -> [N,K] fp16 ----------------
__global__ void wsplit16(const float* __restrict__ w,
                         __half* __restrict__ oh, int K, int N) {
    __shared__ float t[32][33];
    int n0 = blockIdx.x * 32, k0 = blockIdx.y * 32;
    for (int r = threadIdx.y; r < 32; r += 8)
        t[r][threadIdx.x] = w[(size_t)(k0 + r) * N + n0 + threadIdx.x];
    __syncthreads();
    for (int r = threadIdx.y; r < 32; r += 8)
        oh[(size_t)(n0 + r) * K + k0 + threadIdx.x] = __float2half_rn(t[threadIdx.x][r]);
}

// ---------------- HMMA GEMM fp16 2-term, 3-stage pipeline ----------------
// C[M,N] = (Ah+Al)[M,K] @ B[N,K]^T
// EPI 1: C = acc + bias + res                (fp32)
// EPI 2: gelu(acc + bias) -> fp16 hi/lo (Ch/Cl)
// EPI 3: qkv: (acc+bias) * (col<DIMC ? 0.125 : 1) -> Ch always, Cl only col<DIMC
#define STG 24576
#define GEMM_SMEM (3 * STG)   // 73728
template <int EPI>
__global__ __launch_bounds__(256) void gemm_mma(
    const __half* __restrict__ Ah, const __half* __restrict__ Al,
    const __half* __restrict__ B16,
    const float* __restrict__ bias, const float* __restrict__ res,
    float* __restrict__ C, __half* __restrict__ Ch, __half* __restrict__ Cl,
    int M, int N, int K) {
    extern __shared__ char smem[];
    uint32_t sb = smem_u32(smem);
    int tid = threadIdx.x, lane = tid & 31, w = tid >> 5;
    int m0 = blockIdx.y * 128, n0 = blockIdx.x * 128;
    int wm = (w & 3) * 32, wn = (w >> 2) * 64;

    float acc[2][8][4] = {};
    const int nchunk = K >> 5;

    int lr = tid >> 1;
    int ls0 = (tid & 1) * 2;
    uint32_t loff[2];
    #pragma unroll
    for (int j = 0; j < 2; j++) loff[j] = swz(lr, (ls0 + j) * 8);

    auto issue = [&](int c) {
        uint32_t st = sb + (uint32_t)(c % 3) * STG;
        int k0 = c << 5;
        #pragma unroll
        for (int j = 0; j < 2; j++) {
            size_t ga = (size_t)(m0 + lr) * K + k0 + (ls0 + j) * 8;
            size_t gb = (size_t)(n0 + lr) * K + k0 + (ls0 + j) * 8;
            cpa16(st + loff[j],         Ah + ga);
            cpa16(st + 8192 + loff[j],  Al + ga);
            cpa16(st + 16384 + loff[j], B16 + gb);
        }
        CP_COMMIT();
    };
    issue(0);
    if (nchunk > 1) issue(1);

    int rA = (lane & 15);
    int cAh = ((lane >> 4) << 3);
    int rB = (lane & 7) + ((lane >> 4) << 3);
    int cBh = (((lane >> 3) & 1) << 3);

    for (int c = 0; c < nchunk; c++) {
        if (c + 2 < nchunk) issue(c + 2);
        int rem = nchunk - 1 - c;
        if (rem >= 2)      CP_WAIT(2);
        else if (rem == 1) CP_WAIT(1);
        else               CP_WAIT(0);
        __syncthreads();

        uint32_t stg = sb + (uint32_t)(c % 3) * STG;
        #pragma unroll
        for (int ks = 0; ks < 32; ks += 16) {
            uint32_t aH[2][4], aL[2][4];
            #pragma unroll
            for (int tm = 0; tm < 2; tm++) {
                uint32_t ao = swz(wm + tm * 16 + rA, ks + cAh);
                LDSM4(aH[tm], stg + ao);
                LDSM4(aL[tm], stg + 8192 + ao);
            }
            uint32_t bfr[8][2];
            #pragma unroll
            for (int t4 = 0; t4 < 4; t4++) {
                uint32_t q[4];
                LDSM4(q, stg + 16384 + swz(wn + t4 * 16 + rB, ks + cBh));
                bfr[2 * t4][0] = q[0]; bfr[2 * t4][1] = q[1];
                bfr[2 * t4 + 1][0] = q[2]; bfr[2 * t4 + 1][1] = q[3];
            }
            #pragma unroll
            for (int tm = 0; tm < 2; tm++)
                #pragma unroll
                for (int tn = 0; tn < 8; tn++) {
                    MMAF16(acc[tm][tn], aH[tm], bfr[tn]);
                    MMAF16(acc[tm][tn], aL[tm], bfr[tn]);
                }
        }
        __syncthreads();
    }

    #pragma unroll
    for (int tm = 0; tm < 2; tm++) {
        #pragma unroll
        for (int tn = 0; tn < 8; tn++) {
            int row = m0 + wm + tm * 16 + (lane >> 2);
            int col = n0 + wn + tn * 8 + ((lane & 3) << 1);
            float b0 = bias[col], b1 = bias[col + 1];
            float* a = acc[tm][tn];
            #pragma unroll
            for (int hrow = 0; hrow < 2; hrow++) {
                int rr = row + hrow * 8;
                float v0 = a[2 * hrow + 0] + b0;
                float v1 = a[2 * hrow + 1] + b1;
                size_t o = (size_t)rr * N + col;
                if (EPI == 1) {
                    float2 rv = *(const float2*)(res + o);
                    float2 v = {v0 + rv.x, v1 + rv.y};
                    *(float2*)(C + o) = v;
                } else if (EPI == 2) {
                    float g0 = 0.5f * v0 * (1.0f + erff(v0 * 0.70710678118654752f));
                    float g1 = 0.5f * v1 * (1.0f + erff(v1 * 0.70710678118654752f));
                    uint32_t lo;
                    uint32_t hi = packsplith(g0, g1, lo);
                    *(uint32_t*)(Ch + o) = hi;
                    *(uint32_t*)(Cl + o) = lo;
                } else {
                    if (col < DIMC) {   // Q: exact 1/8 pre-scale, keep hi/lo
                        uint32_t lo;
                        uint32_t hi = packsplith(v0 * 0.125f, v1 * 0.125f, lo);
                        *(uint32_t*)(Ch + o) = hi;
                        *(uint32_t*)(Cl + o) = lo;
                    } else {            // K/V: single fp16
                        *(uint32_t*)(Ch + o) = pack16(v0, v1);
                    }
                }
            }
        }
    }
}

// ---------------- tensorized masked flash attention (fp16 2-term) ----------------
// Block: 128 q-rows x 1 head; 8 warps x 16 rows; j-tiles of 64, double-buffered.
// dyn smem: Qh 0 | Ql 16K | stage s at 32K + s*16K: {K 8KB, V 8KB}
#define AQH 0
#define AQL 16384
#define ASTG0 32768
#define ATTN_SM 65536
__global__ __launch_bounds__(256) void attn_mma(
    const __half* __restrict__ qkvH, const __half* __restrict__ qkvL,
    const float* __restrict__ elev, const float* __restrict__ barrier_p,
    __half* __restrict__ outH, __half* __restrict__ outL) {
    extern __shared__ char smem[];
    uint32_t sb = smem_u32(smem);
    __shared__ float eq_s[128], ek_s[2][64];

    int tid = threadIdx.x, lane = tid & 31, w = tid >> 5;
    int q0 = blockIdx.x * 128;
    int h = blockIdx.y;
    int b = blockIdx.z;
    const float bar = barrier_p[0];
    const size_t base3 = (size_t)b * SEQ * (3 * DIMC);
    const int hoff = h * HD;
    const int wm = w * 16;

    // ---- stage Q (pre-scaled hi/lo) ----
    #pragma unroll
    for (int i = 0; i < 8; i++) {
        int ch = tid + 256 * i;
        int arr = ch >> 10, row = (ch >> 3) & 127, c8 = ch & 7;
        const __half* src = (arr ? qkvL : qkvH) + base3 +
            (size_t)(q0 + row) * (3 * DIMC) + hoff + c8 * 8;
        cpa16(sb + (arr ? AQL : AQH) + asw(row, c8 * 8), src);
    }
    // ---- K/V staging (single fp16 each) ----
    auto issueKV = [&](int jt) {
        uint32_t st = sb + ASTG0 + (uint32_t)(jt & 1) * 16384;
        int j0 = jt << 6;
        #pragma unroll
        for (int i = 0; i < 4; i++) {
            int ch = tid + 256 * i;
            int arr = ch >> 9, row = (ch >> 3) & 63, c8 = ch & 7;   // 0=K 1=V
            int coff = arr ? 2 * DIMC : DIMC;
            const __half* src = qkvH + base3 +
                (size_t)(j0 + row) * (3 * DIMC) + coff + hoff + c8 * 8;
            cpa16(st + (uint32_t)arr * 8192 + asw(row, c8 * 8), src);
        }
        CP_COMMIT();
    };
    issueKV(0);
    if (tid < 128) eq_s[tid] = elev[b * SEQ + q0 + tid];
    if (tid < 64) ek_s[0][tid] = elev[b * SEQ + tid];

    float m0 = -1e30f, m1 = -1e30f;
    float P0 = 0.f, P1 = 0.f, S0 = 0.f, S1 = 0.f;
    float oacc[8][4] = {};

    const int rA = lane & 15;
    const int cA = (lane >> 4) << 3;
    const int rB = (lane & 7) + ((lane >> 4) << 3);
    const int cB = ((lane >> 3) & 1) << 3;
    const int vj = (((lane >> 3) & 1) << 3) + (lane & 7);
    const int vd = (lane >> 4) << 3;

    const int NJT = SEQ / 64;
    for (int jt = 0; jt < NJT; jt++) {
        if (jt + 1 < NJT) {
            issueKV(jt + 1);
            if (tid < 64) ek_s[(jt + 1) & 1][tid] = elev[b * SEQ + ((jt + 1) << 6) + tid];
            CP_WAIT(1);
        } else {
            CP_WAIT(0);
        }
        __syncthreads();
        uint32_t stg = sb + ASTG0 + (uint32_t)(jt & 1) * 16384;
        const float* eks = ek_s[jt & 1];

        // ---- scores = (Qh+Ql) @ K^T ----
        float sc[8][4] = {};
        #pragma unroll
        for (int kc = 0; kc < 4; kc++) {
            uint32_t aH4[4], aL4[4];
            uint32_t ao = asw(wm + rA, kc * 16 + cA);
            LDSM4(aH4, sb + AQH + ao);
            LDSM4(aL4, sb + AQL + ao);
            #pragma unroll
            for (int nt2 = 0; nt2 < 4; nt2++) {
                uint32_t bh[4];
                LDSM4(bh, stg + asw(nt2 * 16 + rB, kc * 16 + cB));
                MMAF16(sc[2 * nt2],     aH4, bh);
                MMAF16(sc[2 * nt2],     aL4, bh);
                MMAF16(sc[2 * nt2 + 1], aH4, bh + 2);
                MMAF16(sc[2 * nt2 + 1], aL4, bh + 2);
            }
        }

        // ---- online softmax + elevation mask ----
        float mx0 = -1e30f, mx1 = -1e30f;
        #pragma unroll
        for (int nt = 0; nt < 8; nt++) {
            mx0 = fmaxf(mx0, fmaxf(sc[nt][0], sc[nt][1]));
            mx1 = fmaxf(mx1, fmaxf(sc[nt][2], sc[nt][3]));
        }
        mx0 = fmaxf(mx0, __shfl_xor_sync(0xffffffffu, mx0, 1));
        mx0 = fmaxf(mx0, __shfl_xor_sync(0xffffffffu, mx0, 2));
        mx1 = fmaxf(mx1, __shfl_xor_sync(0xffffffffu, mx1, 1));
        mx1 = fmaxf(mx1, __shfl_xor_sync(0xffffffffu, mx1, 2));
        float mn0 = fmaxf(m0, mx0), mn1 = fmaxf(m1, mx1);
        float f0 = __expf(m0 - mn0), f1 = __expf(m1 - mn1);
        m0 = mn0; m1 = mn1;

        float eq0 = eq_s[wm + (lane >> 2)];
        float eq1 = eq_s[wm + (lane >> 2) + 8];
        float ps0 = 0.f, ps1 = 0.f, ss0 = 0.f, ss1 = 0.f;
        #pragma unroll
        for (int nt = 0; nt < 8; nt++) {
            int jc = nt * 8 + ((lane & 3) << 1);
            float ek0 = eks[jc], ek1 = eks[jc + 1];
            #pragma unroll
            for (int v = 0; v < 4; v++) {
                float mn = (v < 2) ? mn0 : mn1;
                float eq = (v < 2) ? eq0 : eq1;
                float ek = (v & 1) ? ek1 : ek0;
                float e = __expf(sc[nt][v] - mn);
                float msk = fmaxf(__fdividef(1.f, 1.f + __expf(bar * (ek - eq))), 1e-6f);
                float p = e * msk;
                sc[nt][v] = p;
                if (v < 2) { ps0 += p; ss0 += e; } else { ps1 += p; ss1 += e; }
            }
        }
        ps0 += __shfl_xor_sync(0xffffffffu, ps0, 1); ps0 += __shfl_xor_sync(0xffffffffu, ps0, 2);
        ps1 += __shfl_xor_sync(0xffffffffu, ps1, 1); ps1 += __shfl_xor_sync(0xffffffffu, ps1, 2);
        ss0 += __shfl_xor_sync(0xffffffffu, ss0, 1); ss0 += __shfl_xor_sync(0xffffffffu, ss0, 2);
        ss1 += __shfl_xor_sync(0xffffffffu, ss1, 1); ss1 += __shfl_xor_sync(0xffffffffu, ss1, 2);
        P0 = P0 * f0 + ps0; P1 = P1 * f1 + ps1;
        S0 = S0 * f0 + ss0; S1 = S1 * f1 + ss1;
        #pragma unroll
        for (int dt = 0; dt < 8; dt++) {
            oacc[dt][0] *= f0; oacc[dt][1] *= f0;
            oacc[dt][2] *= f1; oacc[dt][3] *= f1;
        }

        // ---- oacc += (Ph+Pl) @ V ----
        #pragma unroll
        for (int kc = 0; kc < 4; kc++) {
            uint32_t ph[4], pl[4];
            ph[0] = packsplith(sc[2 * kc][0],     sc[2 * kc][1],     pl[0]);
            ph[1] = packsplith(sc[2 * kc][2],     sc[2 * kc][3],     pl[1]);
            ph[2] = packsplith(sc[2 * kc + 1][0], sc[2 * kc + 1][1], pl[2]);
            ph[3] = packsplith(sc[2 * kc + 1][2], sc[2 * kc + 1][3], pl[3]);
            #pragma unroll
            for (int dt2 = 0; dt2 < 4; dt2++) {
                uint32_t vh[4];
                LDSM4T(vh, stg + 8192 + asw(kc * 16 + vj, dt2 * 16 + vd));
                MMAF16(oacc[2 * dt2],     ph, vh);
                MMAF16(oacc[2 * dt2],     pl, vh);
                MMAF16(oacc[2 * dt2 + 1], ph, vh + 2);
                MMAF16(oacc[2 * dt2 + 1], pl, vh + 2);
            }
        }
        __syncthreads();
    }

    // ---- writeout: normalize, split fp16 hi/lo ----
    float inv0 = __fdividef(1.f, P0 + 1e-8f * S0);
    float inv1 = __fdividef(1.f, P1 + 1e-8f * S1);
    int r0 = b * SEQ + q0 + wm + (lane >> 2);
    int col = hoff + ((lane & 3) << 1);
    #pragma unroll
    for (int dt = 0; dt < 8; dt++) {
        uint32_t lo;
        uint32_t hi = packsplith(oacc[dt][0] * inv0, oacc[dt][1] * inv0, lo);
        size_t o = (size_t)r0 * DIMC + col + dt * 8;
        *(uint32_t*)(outH + o) = hi;
        *(uint32_t*)(outL + o) = lo;
        hi = packsplith(oacc[dt][2] * inv1, oacc[dt][3] * inv1, lo);
        o += (size_t)8 * DIMC;
        *(uint32_t*)(outH + o) = hi;
        *(uint32_t*)(outL + o) = lo;
    }
}

// ---------------- launch ----------------
extern "C" void kernel_launch(void* const* d_in, const int* in_sizes, int n_in,
                              void* d_out, int out_size) {
    const float* x       = (const float*)d_in[0];
    const float* elev    = (const float*)d_in[1];
    const float* qkv_w   = (const float*)d_in[2];
    const float* qkv_b   = (const float*)d_in[3];
    const float* proj_w  = (const float*)d_in[4];
    const float* proj_b  = (const float*)d_in[5];
    const float* ln1_g   = (const float*)d_in[6];
    const float* ln1_b   = (const float*)d_in[7];
    const float* ln2_g   = (const float*)d_in[8];
    const float* ln2_b   = (const float*)d_in[9];
    const float* fc1_w   = (const float*)d_in[10];
    const float* fc1_b   = (const float*)d_in[11];
    const float* fc2_w   = (const float*)d_in[12];
    const float* fc2_b   = (const float*)d_in[13];
    const float* barrier = (const float*)d_in[14];
    float* out = (float*)d_out;

    __half *aH, *aL, *fH, *fL, *qH, *qL, *wq, *wp, *w1, *w2;
    cudaGetSymbolAddress((void**)&aH, g_aH);   cudaGetSymbolAddress((void**)&aL, g_aL);
    cudaGetSymbolAddress((void**)&fH, g_fH);   cudaGetSymbolAddress((void**)&fL, g_fL);
    cudaGetSymbolAddress((void**)&qH, g_qkvH); cudaGetSymbolAddress((void**)&qL, g_qkvL);
    cudaGetSymbolAddress((void**)&wq, g_wqkv); cudaGetSymbolAddress((void**)&wp, g_wproj);
    cudaGetSymbolAddress((void**)&w1, g_wfc1); cudaGetSymbolAddress((void**)&w2, g_wfc2);

    cudaFuncSetAttribute(gemm_mma<1>, cudaFuncAttributeMaxDynamicSharedMemorySize, GEMM_SMEM);
    cudaFuncSetAttribute(gemm_mma<2>, cudaFuncAttributeMaxDynamicSharedMemorySize, GEMM_SMEM);
    cudaFuncSetAttribute(gemm_mma<3>, cudaFuncAttributeMaxDynamicSharedMemorySize, GEMM_SMEM);
    cudaFuncSetAttribute(attn_mma, cudaFuncAttributeMaxDynamicSharedMemorySize, ATTN_SM);

    dim3 tb(32, 8);
    wsplit16<<<dim3(3 * DIMC / 32, DIMC / 32), tb>>>(qkv_w, wq, DIMC, 3 * DIMC);
    wsplit16<<<dim3(DIMC / 32, DIMC / 32), tb>>>(proj_w, wp, DIMC, DIMC);
    wsplit16<<<dim3(HIDDENC / 32, DIMC / 32), tb>>>(fc1_w, w1, DIMC, HIDDENC);
    wsplit16<<<dim3(DIMC / 32, HIDDENC / 32), tb>>>(fc2_w, w2, HIDDENC, DIMC);

    // 1. LN1 -> splits
    ln_split<<<ROWS, 256>>>(x, ln1_g, ln1_b, aH, aL);
    // 2. QKV -> fp16 (Q pre-scaled + split, K/V single)
    gemm_mma<3><<<dim3(3 * DIMC / 128, ROWS / 128), 256, GEMM_SMEM>>>(
        aH, aL, wq, qkv_b, nullptr, nullptr, qH, qL, ROWS, 3 * DIMC, DIMC);
    // 3. attention -> splits
    attn_mma<<<dim3(SEQ / 128, NHEADS, BATCH), 256, ATTN_SM>>>(qH, qL, elev, barrier, aH, aL);
    // 4. x2 = x + attn @ proj_w + b -> d_out
    gemm_mma<1><<<dim3(DIMC / 128, ROWS / 128), 256, GEMM_SMEM>>>(
        aH, aL, wp, proj_b, x, out, nullptr, nullptr, ROWS, DIMC, DIMC);
    // 5. LN2 -> splits
    ln_split<<<ROWS, 256>>>(out, ln2_g, ln2_b, aH, aL);
    // 6. fc1 + gelu -> splits
    gemm_mma<2><<<dim3(HIDDENC / 128, ROWS / 128), 256, GEMM_SMEM>>>(
        aH, aL, w1, fc1_b, nullptr, nullptr, fH, fL, ROWS, HIDDENC, DIMC);
    // 7. out = x2 + fc1 @ fc2_w + b
    gemm_mma<1><<<dim3(DIMC / 128, ROWS / 128), 256, GEMM_SMEM>>>(
        fH, fL, w2, fc2_b, out, out, nullptr, nullptr, ROWS, DIMC, HIDDENC);
}

// round 16
// speedup vs baseline: 1.5363x; 1.5363x over previous
#include <cuda_runtime.h>
#include <cuda_fp16.h>
#include <math.h>
#include <stdint.h>

#define DIMC 768
#define NHEADS 12
#define HD 64
#define HIDDENC 3072
#define SEQ 2048
#define BATCH 2
#define ROWS (BATCH * SEQ)   // 4096

// ---------------- scratch (device globals) ----------------
__device__ __half g_aH[ROWS * DIMC];
__device__ __half g_aL[ROWS * DIMC];
__device__ __half g_fH[ROWS * HIDDENC];
__device__ __half g_fL[ROWS * HIDDENC];
__device__ __half g_qkvH[ROWS * 3 * DIMC];
__device__ __half g_qkvL[ROWS * 3 * DIMC];   // lo only used for Q region
__device__ __half g_wqkv[3 * DIMC * DIMC];
__device__ __half g_wproj[DIMC * DIMC];
__device__ __half g_wfc1[HIDDENC * DIMC];
__device__ __half g_wfc2[DIMC * HIDDENC];

// ---------------- helpers ----------------
__device__ __forceinline__ uint32_t smem_u32(const void* p) {
    uint32_t a;
    asm("{ .reg .u64 t; cvta.to.shared.u64 t, %1; cvt.u32.u64 %0, t; }" : "=r"(a) : "l"(p));
    return a;
}
__device__ __forceinline__ void cpa16(uint32_t dst, const void* src) {
    asm volatile("cp.async.cg.shared.global [%0], [%1], 16;" :: "r"(dst), "l"(src));
}
#define CP_COMMIT() asm volatile("cp.async.commit_group;" ::: "memory")
#define CP_WAIT(n)  asm volatile("cp.async.wait_group %0;" :: "n"(n) : "memory")

#define LDSM4(r, a) \
    asm volatile("ldmatrix.sync.aligned.m8n8.x4.shared.b16 {%0,%1,%2,%3}, [%4];" \
        : "=r"((r)[0]), "=r"((r)[1]), "=r"((r)[2]), "=r"((r)[3]) : "r"(a))
#define LDSM4T(r, a) \
    asm volatile("ldmatrix.sync.aligned.m8n8.x4.trans.shared.b16 {%0,%1,%2,%3}, [%4];" \
        : "=r"((r)[0]), "=r"((r)[1]), "=r"((r)[2]), "=r"((r)[3]) : "r"(a))

#define MMAF16(d, a, b) \
    asm volatile("mma.sync.aligned.m16n8k16.row.col.f32.f16.f16.f32 " \
        "{%0,%1,%2,%3}, {%4,%5,%6,%7}, {%8,%9}, {%0,%1,%2,%3};" \
        : "+f"((d)[0]), "+f"((d)[1]), "+f"((d)[2]), "+f"((d)[3]) \
        : "r"((a)[0]), "r"((a)[1]), "r"((a)[2]), "r"((a)[3]), "r"((b)[0]), "r"((b)[1]))

__device__ __forceinline__ void split2h(float v, __half& h, __half& l) {
    h = __float2half_rn(v);
    l = __float2half_rn(v - __half2float(h));
}
__device__ __forceinline__ uint32_t packsplith(float a, float b, uint32_t& lo) {
    __half ah, al, bh, bl;
    split2h(a, ah, al);
    split2h(b, bh, bl);
    lo = (uint32_t)__half_as_ushort(al) | ((uint32_t)__half_as_ushort(bl) << 16);
    return (uint32_t)__half_as_ushort(ah) | ((uint32_t)__half_as_ushort(bh) << 16);
}
__device__ __forceinline__ uint32_t pack16(float a, float b) {
    return (uint32_t)__half_as_ushort(__float2half_rn(a)) |
           ((uint32_t)__half_as_ushort(__float2half_rn(b)) << 16);
}

// gemm tile swizzle: [128][32] fp16 packed in 64 x 128B rows
__device__ __forceinline__ uint32_t swz(int r, int c) {
    int p = r >> 1;
    int sub = ((r & 1) << 2) + (c >> 3);
    return (uint32_t)(p * 128 + (((sub ^ (p & 7)) << 4)) + ((c & 7) << 1));
}
// attention tile swizzle: [.][64] fp16, 128B per row (byte offset)
__device__ __forceinline__ uint32_t asw(int r, int c) {
    return (uint32_t)(r * 128 + ((((c >> 3) ^ (r & 7)) << 4)) + ((c & 7) << 1));
}

// ---------------- LayerNorm -> fp16 hi/lo split ----------------
__global__ void ln_split(const float* __restrict__ x,
                         const float* __restrict__ g,
                         const float* __restrict__ b,
                         __half* __restrict__ oh,
                         __half* __restrict__ ol) {
    int row = blockIdx.x;
    const float* xr = x + (size_t)row * DIMC;
    float s = 0.f, s2 = 0.f;
    for (int i = threadIdx.x; i < DIMC; i += 256) {
        float v = xr[i];
        s += v; s2 += v * v;
    }
    #pragma unroll
    for (int o = 16; o; o >>= 1) {
        s  += __shfl_xor_sync(0xffffffffu, s,  o);
        s2 += __shfl_xor_sync(0xffffffffu, s2, o);
    }
    __shared__ float sm[8], sq[8];
    __shared__ float mu_s, rs_s;
    int w = threadIdx.x >> 5, l = threadIdx.x & 31;
    if (l == 0) { sm[w] = s; sq[w] = s2; }
    __syncthreads();
    if (threadIdx.x == 0) {
        float S = 0.f, S2 = 0.f;
        #pragma unroll
        for (int i = 0; i < 8; i++) { S += sm[i]; S2 += sq[i]; }
        float mu = S / DIMC;
        float var = S2 / DIMC - mu * mu;
        mu_s = mu;
        rs_s = rsqrtf(var + 1e-5f);
    }
    __syncthreads();
    float mu = mu_s, rs = rs_s;
    for (int i = threadIdx.x; i < DIMC; i += 256) {
        float v = (xr[i] - mu) * rs * g[i] + b[i];
        __half h, lo;
        split2h(v, h, lo);
        oh[(size_t)row * DIMC + i] = h;
        ol[(size_t)row * DIMC + i] = lo;
    }
}

// ---------------- weight transpose: w[K,N] fp32 -> [N,K] fp16 ----------------
__global__ void wsplit16(const float* __restrict__ w,
                         __half* __restrict__ oh, int K, int N) {
    __shared__ float t[32][33];
    int n0 = blockIdx.x * 32, k0 = blockIdx.y * 32;
    for (int r = threadIdx.y; r < 32; r += 8)
        t[r][threadIdx.x] = w[(size_t)(k0 + r) * N + n0 + threadIdx.x];
    __syncthreads();
    for (int r = threadIdx.y; r < 32; r += 8)
        oh[(size_t)(n0 + r) * K + k0 + threadIdx.x] = __float2half_rn(t[threadIdx.x][r]);
}

// ---------------- HMMA GEMM fp16 2-term (term loop OUTSIDE tile loops) ----------------
// C[M,N] = (Ah+Al)[M,K] @ B[N,K]^T
// EPI 1: C = acc + bias + res                (fp32)
// EPI 2: gelu(acc + bias) -> fp16 hi/lo (Ch/Cl)
// EPI 3: qkv: (acc+bias) * (col<DIMC ? 0.125 : 1) -> Ch always, Cl only col<DIMC
#define STG 24576
#define GEMM_SMEM (3 * STG)   // 73728
template <int EPI>
__global__ __launch_bounds__(256) void gemm_mma(
    const __half* __restrict__ Ah, const __half* __restrict__ Al,
    const __half* __restrict__ B16,
    const float* __restrict__ bias, const float* __restrict__ res,
    float* __restrict__ C, __half* __restrict__ Ch, __half* __restrict__ Cl,
    int M, int N, int K) {
    extern __shared__ char smem[];
    uint32_t sb = smem_u32(smem);
    int tid = threadIdx.x, lane = tid & 31, w = tid >> 5;
    int m0 = blockIdx.y * 128, n0 = blockIdx.x * 128;
    int wm = (w & 3) * 32, wn = (w >> 2) * 64;

    float acc[2][8][4] = {};
    const int nchunk = K >> 5;

    int lr = tid >> 1;
    int ls0 = (tid & 1) * 2;
    uint32_t loff[2];
    #pragma unroll
    for (int j = 0; j < 2; j++) loff[j] = swz(lr, (ls0 + j) * 8);

    auto issue = [&](int c) {
        uint32_t st = sb + (uint32_t)(c % 3) * STG;
        int k0 = c << 5;
        #pragma unroll
        for (int j = 0; j < 2; j++) {
            size_t ga = (size_t)(m0 + lr) * K + k0 + (ls0 + j) * 8;
            size_t gb = (size_t)(n0 + lr) * K + k0 + (ls0 + j) * 8;
            cpa16(st + loff[j],         Ah + ga);
            cpa16(st + 8192 + loff[j],  Al + ga);
            cpa16(st + 16384 + loff[j], B16 + gb);
        }
        CP_COMMIT();
    };
    issue(0);
    if (nchunk > 1) issue(1);

    int rA = (lane & 15);
    int cAh = ((lane >> 4) << 3);
    int rB = (lane & 7) + ((lane >> 4) << 3);
    int cBh = (((lane >> 3) & 1) << 3);

    for (int c = 0; c < nchunk; c++) {
        if (c + 2 < nchunk) issue(c + 2);
        int rem = nchunk - 1 - c;
        if (rem >= 2)      CP_WAIT(2);
        else if (rem == 1) CP_WAIT(1);
        else               CP_WAIT(0);
        __syncthreads();

        uint32_t stg = sb + (uint32_t)(c % 3) * STG;
        #pragma unroll
        for (int ks = 0; ks < 32; ks += 16) {
            uint32_t aH[2][4], aL[2][4];
            #pragma unroll
            for (int tm = 0; tm < 2; tm++) {
                uint32_t ao = swz(wm + tm * 16 + rA, ks + cAh);
                LDSM4(aH[tm], stg + ao);
                LDSM4(aL[tm], stg + 8192 + ao);
            }
            uint32_t bfr[8][2];
            #pragma unroll
            for (int t4 = 0; t4 < 4; t4++) {
                uint32_t q[4];
                LDSM4(q, stg + 16384 + swz(wn + t4 * 16 + rB, ks + cBh));
                bfr[2 * t4][0] = q[0]; bfr[2 * t4][1] = q[1];
                bfr[2 * t4 + 1][0] = q[2]; bfr[2 * t4 + 1][1] = q[3];
            }
            // term H pass: 16 independent accumulators
            #pragma unroll
            for (int tm = 0; tm < 2; tm++)
                #pragma unroll
                for (int tn = 0; tn < 8; tn++)
                    MMAF16(acc[tm][tn], aH[tm], bfr[tn]);
            // term L pass
            #pragma unroll
            for (int tm = 0; tm < 2; tm++)
                #pragma unroll
                for (int tn = 0; tn < 8; tn++)
                    MMAF16(acc[tm][tn], aL[tm], bfr[tn]);
        }
        __syncthreads();
    }

    #pragma unroll
    for (int tm = 0; tm < 2; tm++) {
        #pragma unroll
        for (int tn = 0; tn < 8; tn++) {
            int row = m0 + wm + tm * 16 + (lane >> 2);
            int col = n0 + wn + tn * 8 + ((lane & 3) << 1);
            float b0 = bias[col], b1 = bias[col + 1];
            float* a = acc[tm][tn];
            #pragma unroll
            for (int hrow = 0; hrow < 2; hrow++) {
                int rr = row + hrow * 8;
                float v0 = a[2 * hrow + 0] + b0;
                float v1 = a[2 * hrow + 1] + b1;
                size_t o = (size_t)rr * N + col;
                if (EPI == 1) {
                    float2 rv = *(const float2*)(res + o);
                    float2 v = {v0 + rv.x, v1 + rv.y};
                    *(float2*)(C + o) = v;
                } else if (EPI == 2) {
                    float g0 = 0.5f * v0 * (1.0f + erff(v0 * 0.70710678118654752f));
                    float g1 = 0.5f * v1 * (1.0f + erff(v1 * 0.70710678118654752f));
                    uint32_t lo;
                    uint32_t hi = packsplith(g0, g1, lo);
                    *(uint32_t*)(Ch + o) = hi;
                    *(uint32_t*)(Cl + o) = lo;
                } else {
                    if (col < DIMC) {   // Q: exact 1/8 pre-scale, keep hi/lo
                        uint32_t lo;
                        uint32_t hi = packsplith(v0 * 0.125f, v1 * 0.125f, lo);
                        *(uint32_t*)(Ch + o) = hi;
                        *(uint32_t*)(Cl + o) = lo;
                    } else {            // K/V: single fp16
                        *(uint32_t*)(Ch + o) = pack16(v0, v1);
                    }
                }
            }
        }
    }
}

// ---------------- tensorized masked flash attention (fp16 2-term, reordered) ----------------
// Block: 128 q-rows x 1 head; 8 warps x 16 rows; j-tiles of 64, double-buffered.
// dyn smem: Qh 0 | Ql 16K | stage s at 32K + s*16K: {K 8KB, V 8KB}
#define AQH 0
#define AQL 16384
#define ASTG0 32768
#define ATTN_SM 65536
__global__ __launch_bounds__(256) void attn_mma(
    const __half* __restrict__ qkvH, const __half* __restrict__ qkvL,
    const float* __restrict__ elev, const float* __restrict__ barrier_p,
    __half* __restrict__ outH, __half* __restrict__ outL) {
    extern __shared__ char smem[];
    uint32_t sb = smem_u32(smem);
    __shared__ float eq_s[128], ek_s[2][64];

    int tid = threadIdx.x, lane = tid & 31, w = tid >> 5;
    int q0 = blockIdx.x * 128;
    int h = blockIdx.y;
    int b = blockIdx.z;
    const float bar = barrier_p[0];
    const size_t base3 = (size_t)b * SEQ * (3 * DIMC);
    const int hoff = h * HD;
    const int wm = w * 16;

    // ---- stage Q (pre-scaled hi/lo) ----
    #pragma unroll
    for (int i = 0; i < 8; i++) {
        int ch = tid + 256 * i;
        int arr = ch >> 10, row = (ch >> 3) & 127, c8 = ch & 7;
        const __half* src = (arr ? qkvL : qkvH) + base3 +
            (size_t)(q0 + row) * (3 * DIMC) + hoff + c8 * 8;
        cpa16(sb + (arr ? AQL : AQH) + asw(row, c8 * 8), src);
    }
    // ---- K/V staging ----
    auto issueKV = [&](int jt) {
        uint32_t st = sb + ASTG0 + (uint32_t)(jt & 1) * 16384;
        int j0 = jt << 6;
        #pragma unroll
        for (int i = 0; i < 4; i++) {
            int ch = tid + 256 * i;
            int arr = ch >> 9, row = (ch >> 3) & 63, c8 = ch & 7;   // 0=K 1=V
            int coff = arr ? 2 * DIMC : DIMC;
            const __half* src = qkvH + base3 +
                (size_t)(j0 + row) * (3 * DIMC) + coff + hoff + c8 * 8;
            cpa16(st + (uint32_t)arr * 8192 + asw(row, c8 * 8), src);
        }
        CP_COMMIT();
    };
    issueKV(0);
    if (tid < 128) eq_s[tid] = elev[b * SEQ + q0 + tid];
    if (tid < 64) ek_s[0][tid] = elev[b * SEQ + tid];

    float m0 = -1e30f, m1 = -1e30f;
    float P0 = 0.f, P1 = 0.f, S0 = 0.f, S1 = 0.f;
    float oacc[8][4] = {};

    const int rA = lane & 15;
    const int cA = (lane >> 4) << 3;
    const int rB = (lane & 7) + ((lane >> 4) << 3);
    const int cB = ((lane >> 3) & 1) << 3;
    const int vj = (((lane >> 3) & 1) << 3) + (lane & 7);
    const int vd = (lane >> 4) << 3;

    const int NJT = SEQ / 64;
    for (int jt = 0; jt < NJT; jt++) {
        if (jt + 1 < NJT) {
            issueKV(jt + 1);
            if (tid < 64) ek_s[(jt + 1) & 1][tid] = elev[b * SEQ + ((jt + 1) << 6) + tid];
            CP_WAIT(1);
        } else {
            CP_WAIT(0);
        }
        __syncthreads();
        uint32_t stg = sb + ASTG0 + (uint32_t)(jt & 1) * 16384;
        const float* eks = ek_s[jt & 1];

        // ---- scores = (Qh+Ql) @ K^T : load all K frags, then H pass, then L pass ----
        float sc[8][4] = {};
        #pragma unroll
        for (int kc = 0; kc < 4; kc++) {
            uint32_t aH4[4], aL4[4];
            uint32_t ao = asw(wm + rA, kc * 16 + cA);
            LDSM4(aH4, sb + AQH + ao);
            LDSM4(aL4, sb + AQL + ao);
            uint32_t bh[4][4];
            #pragma unroll
            for (int nt2 = 0; nt2 < 4; nt2++)
                LDSM4(bh[nt2], stg + asw(nt2 * 16 + rB, kc * 16 + cB));
            // H pass: 8 independent accumulators
            #pragma unroll
            for (int nt2 = 0; nt2 < 4; nt2++) {
                MMAF16(sc[2 * nt2],     aH4, bh[nt2]);
                MMAF16(sc[2 * nt2 + 1], aH4, bh[nt2] + 2);
            }
            // L pass
            #pragma unroll
            for (int nt2 = 0; nt2 < 4; nt2++) {
                MMAF16(sc[2 * nt2],     aL4, bh[nt2]);
                MMAF16(sc[2 * nt2 + 1], aL4, bh[nt2] + 2);
            }
        }

        // ---- online softmax + elevation mask ----
        float mx0 = -1e30f, mx1 = -1e30f;
        #pragma unroll
        for (int nt = 0; nt < 8; nt++) {
            mx0 = fmaxf(mx0, fmaxf(sc[nt][0], sc[nt][1]));
            mx1 = fmaxf(mx1, fmaxf(sc[nt][2], sc[nt][3]));
        }
        mx0 = fmaxf(mx0, __shfl_xor_sync(0xffffffffu, mx0, 1));
        mx0 = fmaxf(mx0, __shfl_xor_sync(0xffffffffu, mx0, 2));
        mx1 = fmaxf(mx1, __shfl_xor_sync(0xffffffffu, mx1, 1));
        mx1 = fmaxf(mx1, __shfl_xor_sync(0xffffffffu, mx1, 2));
        float mn0 = fmaxf(m0, mx0), mn1 = fmaxf(m1, mx1);
        float f0 = __expf(m0 - mn0), f1 = __expf(m1 - mn1);
        m0 = mn0; m1 = mn1;

        float eq0 = eq_s[wm + (lane >> 2)];
        float eq1 = eq_s[wm + (lane >> 2) + 8];
        float ps0 = 0.f, ps1 = 0.f, ss0 = 0.f, ss1 = 0.f;
        #pragma unroll
        for (int nt = 0; nt < 8; nt++) {
            int jc = nt * 8 + ((lane & 3) << 1);
            float ek0 = eks[jc], ek1 = eks[jc + 1];
            #pragma unroll
            for (int v = 0; v < 4; v++) {
                float mn = (v < 2) ? mn0 : mn1;
                float eq = (v < 2) ? eq0 : eq1;
                float ek = (v & 1) ? ek1 : ek0;
                float e = __expf(sc[nt][v] - mn);
                float msk = fmaxf(__fdividef(1.f, 1.f + __expf(bar * (ek - eq))), 1e-6f);
                float p = e * msk;
                sc[nt][v] = p;
                if (v < 2) { ps0 += p; ss0 += e; } else { ps1 += p; ss1 += e; }
            }
        }
        ps0 += __shfl_xor_sync(0xffffffffu, ps0, 1); ps0 += __shfl_xor_sync(0xffffffffu, ps0, 2);
        ps1 += __shfl_xor_sync(0xffffffffu, ps1, 1); ps1 += __shfl_xor_sync(0xffffffffu, ps1, 2);
        ss0 += __shfl_xor_sync(0xffffffffu, ss0, 1); ss0 += __shfl_xor_sync(0xffffffffu, ss0, 2);
        ss1 += __shfl_xor_sync(0xffffffffu, ss1, 1); ss1 += __shfl_xor_sync(0xffffffffu, ss1, 2);
        P0 = P0 * f0 + ps0; P1 = P1 * f1 + ps1;
        S0 = S0 * f0 + ss0; S1 = S1 * f1 + ss1;
        #pragma unroll
        for (int dt = 0; dt < 8; dt++) {
            oacc[dt][0] *= f0; oacc[dt][1] *= f0;
            oacc[dt][2] *= f1; oacc[dt][3] *= f1;
        }

        // ---- oacc += (Ph+Pl) @ V : load all V frags, H pass, L pass ----
        #pragma unroll
        for (int kc = 0; kc < 4; kc++) {
            uint32_t ph[4], pl[4];
            ph[0] = packsplith(sc[2 * kc][0],     sc[2 * kc][1],     pl[0]);
            ph[1] = packsplith(sc[2 * kc][2],     sc[2 * kc][3],     pl[1]);
            ph[2] = packsplith(sc[2 * kc + 1][0], sc[2 * kc + 1][1], pl[2]);
            ph[3] = packsplith(sc[2 * kc + 1][2], sc[2 * kc + 1][3], pl[3]);
            uint32_t vh[4][4];
            #pragma unroll
            for (int dt2 = 0; dt2 < 4; dt2++)
                LDSM4T(vh[dt2], stg + 8192 + asw(kc * 16 + vj, dt2 * 16 + vd));
            // H pass: 8 independent accumulators
            #pragma unroll
            for (int dt2 = 0; dt2 < 4; dt2++) {
                MMAF16(oacc[2 * dt2],     ph, vh[dt2]);
                MMAF16(oacc[2 * dt2 + 1], ph, vh[dt2] + 2);
            }
            // L pass
            #pragma unroll
            for (int dt2 = 0; dt2 < 4; dt2++) {
                MMAF16(oacc[2 * dt2],     pl, vh[dt2]);
                MMAF16(oacc[2 * dt2 + 1], pl, vh[dt2] + 2);
            }
        }
        __syncthreads();
    }

    // ---- writeout: normalize, split fp16 hi/lo ----
    float inv0 = __fdividef(1.f, P0 + 1e-8f * S0);
    float inv1 = __fdividef(1.f, P1 + 1e-8f * S1);
    int r0 = b * SEQ + q0 + wm + (lane >> 2);
    int col = hoff + ((lane & 3) << 1);
    #pragma unroll
    for (int dt = 0; dt < 8; dt++) {
        uint32_t lo;
        uint32_t hi = packsplith(oacc[dt][0] * inv0, oacc[dt][1] * inv0, lo);
        size_t o = (size_t)r0 * DIMC + col + dt * 8;
        *(uint32_t*)(outH + o) = hi;
        *(uint32_t*)(outL + o) = lo;
        hi = packsplith(oacc[dt][2] * inv1, oacc[dt][3] * inv1, lo);
        o += (size_t)8 * DIMC;
        *(uint32_t*)(outH + o) = hi;
        *(uint32_t*)(outL + o) = lo;
    }
}

// ---------------- launch ----------------
extern "C" void kernel_launch(void* const* d_in, const int* in_sizes, int n_in,
                              void* d_out, int out_size) {
    const float* x       = (const float*)d_in[0];
    const float* elev    = (const float*)d_in[1];
    const float* qkv_w   = (const float*)d_in[2];
    const float* qkv_b   = (const float*)d_in[3];
    const float* proj_w  = (const float*)d_in[4];
    const float* proj_b  = (const float*)d_in[5];
    const float* ln1_g   = (const float*)d_in[6];
    const float* ln1_b   = (const float*)d_in[7];
    const float* ln2_g   = (const float*)d_in[8];
    const float* ln2_b   = (const float*)d_in[9];
    const float* fc1_w   = (const float*)d_in[10];
    const float* fc1_b   = (const float*)d_in[11];
    const float* fc2_w   = (const float*)d_in[12];
    const float* fc2_b   = (const float*)d_in[13];
    const float* barrier = (const float*)d_in[14];
    float* out = (float*)d_out;

    __half *aH, *aL, *fH, *fL, *qH, *qL, *wq, *wp, *w1, *w2;
    cudaGetSymbolAddress((void**)&aH, g_aH);   cudaGetSymbolAddress((void**)&aL, g_aL);
    cudaGetSymbolAddress((void**)&fH, g_fH);   cudaGetSymbolAddress((void**)&fL, g_fL);
    cudaGetSymbolAddress((void**)&qH, g_qkvH); cudaGetSymbolAddress((void**)&qL, g_qkvL);
    cudaGetSymbolAddress((void**)&wq, g_wqkv); cudaGetSymbolAddress((void**)&wp, g_wproj);
    cudaGetSymbolAddress((void**)&w1, g_wfc1); cudaGetSymbolAddress((void**)&w2, g_wfc2);

    cudaFuncSetAttribute(gemm_mma<1>, cudaFuncAttributeMaxDynamicSharedMemorySize, GEMM_SMEM);
    cudaFuncSetAttribute(gemm_mma<2>, cudaFuncAttributeMaxDynamicSharedMemorySize, GEMM_SMEM);
    cudaFuncSetAttribute(gemm_mma<3>, cudaFuncAttributeMaxDynamicSharedMemorySize, GEMM_SMEM);
    cudaFuncSetAttribute(attn_mma, cudaFuncAttributeMaxDynamicSharedMemorySize, ATTN_SM);

    dim3 tb(32, 8);
    wsplit16<<<dim3(3 * DIMC / 32, DIMC / 32), tb>>>(qkv_w, wq, DIMC, 3 * DIMC);
    wsplit16<<<dim3(DIMC / 32, DIMC / 32), tb>>>(proj_w, wp, DIMC, DIMC);
    wsplit16<<<dim3(HIDDENC / 32, DIMC / 32), tb>>>(fc1_w, w1, DIMC, HIDDENC);
    wsplit16<<<dim3(DIMC / 32, HIDDENC / 32), tb>>>(fc2_w, w2, HIDDENC, DIMC);

    // 1. LN1 -> splits
    ln_split<<<ROWS, 256>>>(x, ln1_g, ln1_b, aH, aL);
    // 2. QKV -> fp16 (Q pre-scaled + split, K/V single)
    gemm_mma<3><<<dim3(3 * DIMC / 128, ROWS / 128), 256, GEMM_SMEM>>>(
        aH, aL, wq, qkv_b, nullptr, nullptr, qH, qL, ROWS, 3 * DIMC, DIMC);
    // 3. attention -> splits
    attn_mma<<<dim3(SEQ / 128, NHEADS, BATCH), 256, ATTN_SM>>>(qH, qL, elev, barrier, aH, aL);
    // 4. x2 = x + attn @ proj_w + b -> d_out
    gemm_mma<1><<<dim3(DIMC / 128, ROWS / 128), 256, GEMM_SMEM>>>(
        aH, aL, wp, proj_b, x, out, nullptr, nullptr, ROWS, DIMC, DIMC);
    // 5. LN2 -> splits
    ln_split<<<ROWS, 256>>>(out, ln2_g, ln2_b, aH, aL);
    // 6. fc1 + gelu -> splits
    gemm_mma<2><<<dim3(HIDDENC / 128, ROWS / 128), 256, GEMM_SMEM>>>(
        aH, aL, w1, fc1_b, nullptr, nullptr, fH, fL, ROWS, HIDDENC, DIMC);
    // 7. out = x2 + fc1 @ fc2_w + b
    gemm_mma<1><<<dim3(DIMC / 128, ROWS / 128), 256, GEMM_SMEM>>>(
        fH, fL, w2, fc2_b, out, out, nullptr, nullptr, ROWS, DIMC, HIDDENC);
}